// round 3
// baseline (speedup 1.0000x reference)
#include <cuda_runtime.h>
#include <cstdint>

// LightGCN layer: dual scatter-add over COO edges.
//   out_users[u] += val * item_emb[i]   for each edge (u, i, val)
//   out_items[i] += val * user_emb[u]
//
// Strategy: embeddings (76 MB) are L2-resident; use vectorized
// red.global.add.v4.f32 to minimize atomic issue count.

__global__ void __launch_bounds__(256) zero_out_kernel(float4* __restrict__ out, int n4)
{
    int i = blockIdx.x * blockDim.x + threadIdx.x;
    if (i < n4) {
        out[i] = make_float4(0.f, 0.f, 0.f, 0.f);
    }
}

__device__ __forceinline__ void red_add_v4(float* dst, float4 x)
{
    asm volatile("red.global.add.v4.f32 [%0], {%1, %2, %3, %4};"
                 :: "l"(dst), "f"(x.x), "f"(x.y), "f"(x.z), "f"(x.w)
                 : "memory");
}

__global__ void __launch_bounds__(256) lightgcn_scatter_kernel(
    const float4* __restrict__ user_emb,   // [NUM_USERS, 16] as float4
    const float4* __restrict__ item_emb,   // [NUM_ITEMS, 16] as float4
    const int*    __restrict__ edge_user,  // [E]
    const int*    __restrict__ edge_item,  // [E]
    const float*  __restrict__ edge_val,   // [E]
    float*        __restrict__ out_users,  // [NUM_USERS, 64]
    float*        __restrict__ out_items,  // [NUM_ITEMS, 64]
    int E)
{
    const int lane      = threadIdx.x & 31;
    const int warp_id   = (blockIdx.x * blockDim.x + threadIdx.x) >> 5;
    const int num_warps = (gridDim.x * blockDim.x) >> 5;
    const int half      = lane >> 4;   // 0: item->user direction, 1: user->item
    const int j         = lane & 15;   // float4 slot within the 64-float row

    for (int e = warp_id; e < E; e += num_warps) {
        // Warp-uniform scalar loads (L1 broadcast)
        const int   u  = edge_user[e];
        const int   it = edge_item[e];
        const float v  = edge_val[e];

        if (half == 0) {
            // gather item row, scale, scatter into user row
            float4 x = item_emb[it * 16 + j];
            x.x *= v; x.y *= v; x.z *= v; x.w *= v;
            red_add_v4(out_users + ((size_t)u * 64 + j * 4), x);
        } else {
            // gather user row, scale, scatter into item row
            float4 x = user_emb[u * 16 + j];
            x.x *= v; x.y *= v; x.z *= v; x.w *= v;
            red_add_v4(out_items + ((size_t)it * 64 + j * 4), x);
        }
    }
}

extern "C" void kernel_launch(void* const* d_in, const int* in_sizes, int n_in,
                              void* d_out, int out_size)
{
    const float* user_emb  = (const float*)d_in[0];   // [200000, 64]
    const float* item_emb  = (const float*)d_in[1];   // [100000, 64]
    const int*   edge_user = (const int*)  d_in[2];   // [E]
    const int*   edge_item = (const int*)  d_in[3];   // [E]
    const float* edge_val  = (const float*)d_in[4];   // [E]

    const int E         = in_sizes[2];
    const int num_users = in_sizes[0] / 64;
    const int num_items = in_sizes[1] / 64;

    float* out_users = (float*)d_out;                       // [num_users, 64]
    float* out_items = (float*)d_out + (size_t)num_users * 64;  // [num_items, 64]

    // 1) zero the output (harness poisons it)
    {
        int n4 = out_size / 4;
        int blocks = (n4 + 255) / 256;
        zero_out_kernel<<<blocks, 256>>>((float4*)d_out, n4);
    }

    // 2) dual-direction scatter-add
    {
        // ~148 SMs; oversubscribe for latency hiding on the L2-bound gathers
        int blocks = 2048;
        lightgcn_scatter_kernel<<<blocks, 256>>>(
            (const float4*)user_emb, (const float4*)item_emb,
            edge_user, edge_item, edge_val,
            out_users, out_items, E);
    }
}

// round 6
// speedup vs baseline: 1.2225x; 1.2225x over previous
#include <cuda_runtime.h>
#include <cstdint>

// LightGCN layer: dual scatter-add over COO edges, split into two passes so
// each pass's random-access working set (gather table + scatter output)
// fits inside the 126 MB L2:
//   pass 1: out_users[u] += val * item_emb[i]   (25 MB + 51 MB)
//   pass 2: out_items[i] += val * user_emb[u]   (51 MB + 25 MB)
// Zero-init of each output half runs right before its pass, priming L2 with
// the output lines the atomics are about to hit.

__global__ void __launch_bounds__(256) zero_kernel(float4* __restrict__ out, int n4)
{
    int i = blockIdx.x * blockDim.x + threadIdx.x;
    int stride = gridDim.x * blockDim.x;
    for (; i < n4; i += stride)
        out[i] = make_float4(0.f, 0.f, 0.f, 0.f);
}

__device__ __forceinline__ void red_add_v4(float* dst, float4 x)
{
    asm volatile("red.global.add.v4.f32 [%0], {%1, %2, %3, %4};"
                 :: "l"(dst), "f"(x.x), "f"(x.y), "f"(x.z), "f"(x.w)
                 : "memory");
}

// One direction of the scatter: out[dst] += val * src_emb[src].
// Each 16-thread group owns one edge; lane j handles float4 slot j of the
// 64-float row (256 B, two coalesced 128 B lines).
__global__ void __launch_bounds__(256) scatter_pass_kernel(
    const float4* __restrict__ src_emb,   // [N_src, 16] as float4
    const int*    __restrict__ edge_src,  // [E] gather index
    const int*    __restrict__ edge_dst,  // [E] scatter index
    const float*  __restrict__ edge_val,  // [E]
    float*        __restrict__ out,       // [N_dst, 64]
    int E)
{
    const int tid    = blockIdx.x * blockDim.x + threadIdx.x;
    const int stride = gridDim.x * blockDim.x;
    const long total = (long)E * 16;

    for (long idx = tid; idx < total; idx += stride) {
        const int e = (int)(idx >> 4);
        const int j = (int)(idx & 15);

        // 16-thread-uniform scalar loads (broadcast within the group)
        const int   s = edge_src[e];
        const int   d = edge_dst[e];
        const float v = edge_val[e];

        float4 x = src_emb[(size_t)s * 16 + j];
        x.x *= v; x.y *= v; x.z *= v; x.w *= v;
        red_add_v4(out + ((size_t)d * 64 + j * 4), x);
    }
}

extern "C" void kernel_launch(void* const* d_in, const int* in_sizes, int n_in,
                              void* d_out, int out_size)
{
    const float* user_emb  = (const float*)d_in[0];   // [200000, 64]
    const float* item_emb  = (const float*)d_in[1];   // [100000, 64]
    const int*   edge_user = (const int*)  d_in[2];   // [E]
    const int*   edge_item = (const int*)  d_in[3];   // [E]
    const float* edge_val  = (const float*)d_in[4];   // [E]

    const int E         = in_sizes[2];
    const int num_users = in_sizes[0] / 64;
    const int num_items = in_sizes[1] / 64;

    float* out_users = (float*)d_out;                           // [num_users, 64]
    float* out_items = (float*)d_out + (size_t)num_users * 64;  // [num_items, 64]

    const int SCATTER_BLOCKS = 2048;   // full occupancy + latency hiding

    // ---- Pass 1: items -> users (working set: item_emb 25MB + out_users 51MB)
    {
        int n4 = (num_users * 64) / 4;
        zero_kernel<<<592, 256>>>((float4*)out_users, n4);
        scatter_pass_kernel<<<SCATTER_BLOCKS, 256>>>(
            (const float4*)item_emb, edge_item, edge_user, edge_val,
            out_users, E);
    }

    // ---- Pass 2: users -> items (working set: user_emb 51MB + out_items 25MB)
    {
        int n4 = (num_items * 64) / 4;
        zero_kernel<<<592, 256>>>((float4*)out_items, n4);
        scatter_pass_kernel<<<SCATTER_BLOCKS, 256>>>(
            (const float4*)user_emb, edge_user, edge_item, edge_val,
            out_items, E);
    }
}